// round 3
// baseline (speedup 1.0000x reference)
#include <cuda_runtime.h>
#include <math.h>

// Problem constants
#define BB 32
#define HW 12544          // 112*112
#define CC 128
#define RR 2048
#define CHUNKS 56
#define POS_PER_BLOCK (HW / CHUNKS)   // 224
#define N4_TOTAL (BB * HW * (CC/4))   // 12,845,056 float4s

// Scratch (device globals: no allocation allowed)
__device__ float g_partial[BB * CHUNKS * CC];
__device__ float g_gate[BB * CC];

// ---------------------------------------------------------------------------
// Kernel 1: partial global-average-pool. Each block sums POS_PER_BLOCK spatial
// positions for one (batch, chunk) over all 128 channels. Fully coalesced
// float4 reads; smem reduce; one float4 store per channel-quad.
// ---------------------------------------------------------------------------
__global__ void __launch_bounds__(256) pool_kernel(const float* __restrict__ x) {
    const int blk   = blockIdx.x;           // 0 .. B*CHUNKS-1
    const int b     = blk / CHUNKS;
    const int chunk = blk % CHUNKS;
    const int t     = threadIdx.x;          // 256
    const int lane  = t & 31;               // channel quad (c/4)
    const int grp   = t >> 5;               // 0..7 position offset

    const float4* xb = (const float4*)x
        + (size_t)b * HW * (CC/4)
        + (size_t)chunk * POS_PER_BLOCK * (CC/4);

    float4 acc = make_float4(0.f, 0.f, 0.f, 0.f);
    #pragma unroll 7
    for (int p = grp; p < POS_PER_BLOCK; p += 8) {
        float4 v = xb[(size_t)p * (CC/4) + lane];
        acc.x += v.x; acc.y += v.y; acc.z += v.z; acc.w += v.w;
    }

    __shared__ float4 sm[256];
    sm[t] = acc;
    __syncthreads();

    if (t < 32) {
        float4 s = sm[t];
        #pragma unroll
        for (int j = 1; j < 8; j++) {
            float4 v = sm[t + 32 * j];
            s.x += v.x; s.y += v.y; s.z += v.z; s.w += v.w;
        }
        ((float4*)g_partial)[(size_t)blk * 32 + t] = s;
    }
}

// ---------------------------------------------------------------------------
// Kernel 2: fused excite. One block per batch, 1024 threads.
//   stage 0: reduce 56 partials -> mean s[128]   (smem, parallel over t)
//   stage 1: h[r] = gelu_tanh(s . w1[:,r] + b1[r]), 2 r per thread (coalesced)
//   stage 2: g[c] = sigmoid(sum_r h[r] w2[r][c] + b2[c])  (8-way split + reduce)
// ---------------------------------------------------------------------------
__global__ void __launch_bounds__(1024) excite_kernel(
    const float* __restrict__ w1, const float* __restrict__ b1,
    const float* __restrict__ w2, const float* __restrict__ b2)
{
    const int b = blockIdx.x;
    const int t = threadIdx.x;

    __shared__ float s[CC];
    __shared__ float h[RR];
    __shared__ float red[1024];

    // stage 0: mean.  thread t: channel c = t&127, chunk-group = t>>7 (7 chunks)
    {
        const int c  = t & 127;
        const int kg = t >> 7;             // 0..7
        float sum = 0.f;
        const float* p = g_partial + (size_t)b * CHUNKS * CC + c;
        #pragma unroll
        for (int k = kg * 7; k < kg * 7 + 7; k++) sum += p[(size_t)k * CC];
        red[t] = sum;
    }
    __syncthreads();
    if (t < CC) {
        float sum = 0.f;
        #pragma unroll
        for (int j = 0; j < 8; j++) sum += red[t + 128 * j];
        s[t] = sum * (1.0f / (float)HW);
    }
    __syncthreads();

    // stage 1: fc1 + gelu, 2 r per thread (r = t and t + 1024; coalesced w1)
    #pragma unroll
    for (int rr = 0; rr < 2; rr++) {
        const int r = rr * 1024 + t;
        float acc = b1[r];
        #pragma unroll
        for (int c = 0; c < CC; c++)
            acc = fmaf(s[c], w1[(size_t)c * RR + r], acc);
        const float u = acc;
        const float inner = 0.7978845608028654f * (u + 0.044715f * u * u * u);
        h[r] = 0.5f * u * (1.0f + tanhf(inner));
    }
    __syncthreads();

    // stage 2: fc2 + sigmoid.  thread (c = t&127, chunk = t>>7) does 256 r.
    {
        const int c     = t & 127;
        const int chunk = t >> 7;
        const float* hp  = h + chunk * 256;
        const float* w2p = w2 + (size_t)chunk * 256 * CC + c;
        float acc = 0.f;
        #pragma unroll 8
        for (int r = 0; r < 256; r++)
            acc = fmaf(hp[r], w2p[(size_t)r * CC], acc);
        red[t] = acc;
    }
    __syncthreads();

    if (t < CC) {
        float v = b2[t];
        #pragma unroll
        for (int j = 0; j < 8; j++) v += red[t + 128 * j];
        g_gate[b * CC + t] = 1.0f / (1.0f + expf(-v));
    }
}

// ---------------------------------------------------------------------------
// Kernel 3: out = x * gate[b, c].  2 independent float4s per thread for MLP.
// ---------------------------------------------------------------------------
__global__ void __launch_bounds__(256) scale_kernel(const float* __restrict__ x,
                                                    float* __restrict__ out) {
    const unsigned base = (blockIdx.x * 256u + threadIdx.x) * 2u;  // float4 idx
    if (base >= (unsigned)N4_TOTAL) return;

    const unsigned b  = base / (HW * (CC / 4));   // both elems same batch
    const unsigned c4 = base & 31u;               // consecutive quads

    float4 v0 = ((const float4*)x)[base];
    float4 v1 = ((const float4*)x)[base + 1];
    const float4 ga = ((const float4*)g_gate)[b * 32 + c4];
    const float4 gb = ((const float4*)g_gate)[b * 32 + ((c4 + 1) & 31u)];
    v0.x *= ga.x; v0.y *= ga.y; v0.z *= ga.z; v0.w *= ga.w;
    v1.x *= gb.x; v1.y *= gb.y; v1.z *= gb.z; v1.w *= gb.w;
    ((float4*)out)[base]     = v0;
    ((float4*)out)[base + 1] = v1;
}

// ---------------------------------------------------------------------------
extern "C" void kernel_launch(void* const* d_in, const int* in_sizes, int n_in,
                              void* d_out, int out_size) {
    const float* x  = (const float*)d_in[0];
    const float* w1 = (const float*)d_in[1];
    const float* b1 = (const float*)d_in[2];
    const float* w2 = (const float*)d_in[3];
    const float* b2 = (const float*)d_in[4];
    float* out = (float*)d_out;

    pool_kernel<<<BB * CHUNKS, 256>>>(x);
    excite_kernel<<<BB, 1024>>>(w1, b1, w2, b2);
    scale_kernel<<<(N4_TOTAL / 2 + 255) / 256, 256>>>(x, out);
}

// round 4
// speedup vs baseline: 1.0917x; 1.0917x over previous
#include <cuda_runtime.h>
#include <math.h>

// Problem constants
#define BB 32
#define HW 12544          // 112*112
#define CC 128
#define RR 2048
#define CHUNKS 56
#define POS_PER_BLOCK (HW / CHUNKS)   // 224
#define N4_TOTAL (BB * HW * (CC/4))   // 12,845,056 float4s (= 50176 * 256)
#define POOL_BLOCKS (BB * CHUNKS)     // 1792
#define PF_BLOCKS 64                  // weight-prefetch blocks appended to pool

// Scratch (device globals: no allocation allowed)
__device__ float g_partial[BB * CHUNKS * CC];  // pool partial sums
__device__ float g_p2[BB * 8 * CC];            // fc2 partials (pre-sigmoid)
__device__ float g_dummy[4];                   // DCE guard for prefetch

// ---------------------------------------------------------------------------
// Kernel 1: partial global-average-pool (+ w1/w2 L2 prefetch in spare blocks).
// Pool blocks: sum 224 spatial positions for one (batch, chunk) over all 128
// channels; coalesced float4 reads; smem reduce; one float4 store per quad.
// Prefetch blocks: stream w1/w2 with __ldcg to warm L2 for the excite kernel.
// ---------------------------------------------------------------------------
__global__ void __launch_bounds__(256) pool_kernel(const float* __restrict__ x,
                                                   const float* __restrict__ w1,
                                                   const float* __restrict__ w2) {
    const int blk = blockIdx.x;
    const int t   = threadIdx.x;

    if (blk >= POOL_BLOCKS) {
        // ---- weight prefetch into L2 ----
        const int pf = blk - POOL_BLOCKS;                 // 0..63
        const int stride = PF_BLOCKS * 256;               // float4 stride
        const float4* w1v = (const float4*)w1;            // 524288 float4
        const float4* w2v = (const float4*)w2;            // 524288 float4
        float acc = 0.f;
        for (int i = pf * 256 + t; i < (CC * RR) / 4; i += stride) {
            float4 a = __ldcg(&w1v[i]);
            float4 b = __ldcg(&w2v[i]);
            acc += a.x + b.x;
        }
        if (acc == 1234567.891f) g_dummy[0] = acc;        // never taken; keeps loads
        return;
    }

    const int b     = blk / CHUNKS;
    const int chunk = blk % CHUNKS;
    const int lane  = t & 31;               // channel quad (c/4)
    const int grp   = t >> 5;               // 0..7 position offset

    const float4* xb = (const float4*)x
        + (size_t)b * HW * (CC/4)
        + (size_t)chunk * POS_PER_BLOCK * (CC/4);

    float4 acc = make_float4(0.f, 0.f, 0.f, 0.f);
    #pragma unroll 7
    for (int p = grp; p < POS_PER_BLOCK; p += 8) {
        float4 v = xb[(size_t)p * (CC/4) + lane];
        acc.x += v.x; acc.y += v.y; acc.z += v.z; acc.w += v.w;
    }

    __shared__ float4 sm[256];
    sm[t] = acc;
    __syncthreads();

    if (t < 32) {
        float4 s = sm[t];
        #pragma unroll
        for (int j = 1; j < 8; j++) {
            float4 v = sm[t + 32 * j];
            s.x += v.x; s.y += v.y; s.z += v.z; s.w += v.w;
        }
        ((float4*)g_partial)[(size_t)blk * 32 + t] = s;
    }
}

// ---------------------------------------------------------------------------
// Kernel 2: excite middle. grid = (8 r-chunks, 32 batches) = 256 blocks x 256.
//   stage 0: reduce 56 pool partials -> mean s[128]
//   stage 1: thread t computes h[cx*256+t] = gelu_tanh(s . w1[:,r] + b1[r])
//            (coalesced w1 reads, L2-warm from prefetch)
//   stage 2: thread (c=t&127, half=t>>7) accumulates its chunk's 128 r of
//            h*w2 -> pair-reduce -> g_p2[b][cx][c]   (pre-bias/sigmoid)
// ---------------------------------------------------------------------------
__global__ void __launch_bounds__(256) excite_kernel(
    const float* __restrict__ w1, const float* __restrict__ b1,
    const float* __restrict__ w2)
{
    const int cx = blockIdx.x;   // 0..7 (chunk of 256 r)
    const int b  = blockIdx.y;   // batch
    const int t  = threadIdx.x;  // 0..255

    __shared__ float s[CC];
    __shared__ float h[256];
    __shared__ float red[256];

    // stage 0: mean over spatial
    {
        const int c  = t & 127;
        const int kg = t >> 7;                 // 0 or 1 -> 28 chunks each
        float sum = 0.f;
        const float* p = g_partial + (size_t)b * CHUNKS * CC + (size_t)kg * 28 * CC + c;
        #pragma unroll 14
        for (int k = 0; k < 28; k++) sum += p[(size_t)k * CC];
        red[t] = sum;
    }
    __syncthreads();
    if (t < CC) s[t] = (red[t] + red[t + 128]) * (1.0f / (float)HW);
    __syncthreads();

    // stage 1: fc1 + gelu for r = cx*256 + t
    {
        const int r = cx * 256 + t;
        float acc = b1[r];
        #pragma unroll
        for (int c = 0; c < CC; c++)
            acc = fmaf(s[c], w1[(size_t)c * RR + r], acc);
        const float u = acc;
        const float inner = 0.7978845608028654f * (u + 0.044715f * u * u * u);
        h[t] = 0.5f * u * (1.0f + tanhf(inner));
    }
    __syncthreads();

    // stage 2: fc2 partial over this chunk's 256 r (split in two halves)
    {
        const int c    = t & 127;
        const int half = t >> 7;
        const float* hp  = h + half * 128;
        const float* w2p = w2 + ((size_t)cx * 256 + half * 128) * CC + c;
        float acc = 0.f;
        #pragma unroll 8
        for (int r = 0; r < 128; r++)
            acc = fmaf(hp[r], w2p[(size_t)r * CC], acc);
        red[t] = acc;
    }
    __syncthreads();

    if (t < CC)
        g_p2[((size_t)b * 8 + cx) * CC + t] = red[t] + red[t + 128];
}

// ---------------------------------------------------------------------------
// Kernel 3: scale. Prologue: finalize gate (sum 8 fc2 partials + bias ->
// sigmoid) into smem; then out = x * gate[b, c], one float4 per thread.
// Each block = 256 float4 = 8 spatial positions, entirely inside one batch.
// ---------------------------------------------------------------------------
__global__ void __launch_bounds__(256) scale_kernel(const float* __restrict__ x,
                                                    const float* __restrict__ b2,
                                                    float* __restrict__ out) {
    const unsigned bid = blockIdx.x;
    const unsigned b   = bid / (HW * (CC / 4) / 256);   // bid / 1568
    const int t = threadIdx.x;

    __shared__ float4 sg[CC / 4];
    if (t < CC) {
        float v = b2[t];
        const float* p = g_p2 + (size_t)b * 8 * CC + t;
        #pragma unroll
        for (int j = 0; j < 8; j++) v += p[(size_t)j * CC];
        ((float*)sg)[t] = 1.0f / (1.0f + expf(-v));
    }
    __syncthreads();

    const unsigned idx = bid * 256u + (unsigned)t;       // float4 index
    float4 v = ((const float4*)x)[idx];
    const float4 g = sg[t & 31];                         // (idx & 31) == (t & 31)
    v.x *= g.x; v.y *= g.y; v.z *= g.z; v.w *= g.w;
    ((float4*)out)[idx] = v;
}

// ---------------------------------------------------------------------------
extern "C" void kernel_launch(void* const* d_in, const int* in_sizes, int n_in,
                              void* d_out, int out_size) {
    const float* x  = (const float*)d_in[0];
    const float* w1 = (const float*)d_in[1];
    const float* b1 = (const float*)d_in[2];
    const float* w2 = (const float*)d_in[3];
    const float* b2 = (const float*)d_in[4];
    float* out = (float*)d_out;

    pool_kernel<<<POOL_BLOCKS + PF_BLOCKS, 256>>>(x, w1, w2);
    excite_kernel<<<dim3(8, BB), 256>>>(w1, b1, w2);
    scale_kernel<<<N4_TOTAL / 256, 256>>>(x, b2, out);
}

// round 5
// speedup vs baseline: 1.0962x; 1.0041x over previous
#include <cuda_runtime.h>
#include <math.h>

// Problem constants
#define BB 32
#define HW 12544          // 112*112
#define CC 128
#define RR 2048
#define CHUNKS 56
#define POS_PER_BLOCK (HW / CHUNKS)   // 224
#define N4_TOTAL (BB * HW * (CC/4))   // 12,845,056 float4s (= 50176 * 256)
#define POOL_BLOCKS (BB * CHUNKS)     // 1792
#define PF_BLOCKS 64                  // weight-prefetch blocks appended to pool

// Scratch (device globals: no allocation allowed)
__device__ float g_partial[BB * CHUNKS * CC];  // pool partial sums
__device__ float g_p2[BB * 8 * CC];            // fc2 partials (pre-sigmoid)
__device__ float g_dummy[4];                   // DCE guard for prefetch

// ---------------------------------------------------------------------------
// Kernel 1: partial global-average-pool (+ w1/w2 L2 prefetch in spare blocks).
// Triggers PDL completion immediately so the excite grid pre-launches.
// ---------------------------------------------------------------------------
__global__ void __launch_bounds__(256) pool_kernel(const float* __restrict__ x,
                                                   const float* __restrict__ w1,
                                                   const float* __restrict__ w2) {
    cudaTriggerProgrammaticLaunchCompletion();

    const int blk = blockIdx.x;
    const int t   = threadIdx.x;

    if (blk >= POOL_BLOCKS) {
        // ---- weight prefetch into L2 ----
        const int pf = blk - POOL_BLOCKS;                 // 0..63
        const int stride = PF_BLOCKS * 256;               // float4 stride
        const float4* w1v = (const float4*)w1;            // 524288 float4
        const float4* w2v = (const float4*)w2;            // 524288 float4
        float acc = 0.f;
        for (int i = pf * 256 + t; i < (CC * RR) / 4; i += stride) {
            float4 a = __ldcg(&w1v[i]);
            float4 b = __ldcg(&w2v[i]);
            acc += a.x + b.x;
        }
        if (acc == 1234567.891f) g_dummy[0] = acc;        // never taken; keeps loads
        return;
    }

    const int b     = blk / CHUNKS;
    const int chunk = blk % CHUNKS;
    const int lane  = t & 31;               // channel quad (c/4)
    const int grp   = t >> 5;               // 0..7 position offset

    const float4* xb = (const float4*)x
        + (size_t)b * HW * (CC/4)
        + (size_t)chunk * POS_PER_BLOCK * (CC/4);

    float4 acc = make_float4(0.f, 0.f, 0.f, 0.f);
    #pragma unroll 7
    for (int p = grp; p < POS_PER_BLOCK; p += 8) {
        float4 v = xb[(size_t)p * (CC/4) + lane];
        acc.x += v.x; acc.y += v.y; acc.z += v.z; acc.w += v.w;
    }

    __shared__ float4 sm[256];
    sm[t] = acc;
    __syncthreads();

    if (t < 32) {
        float4 s = sm[t];
        #pragma unroll
        for (int j = 1; j < 8; j++) {
            float4 v = sm[t + 32 * j];
            s.x += v.x; s.y += v.y; s.z += v.z; s.w += v.w;
        }
        ((float4*)g_partial)[(size_t)blk * 32 + t] = s;
    }
}

// ---------------------------------------------------------------------------
// Kernel 2: excite middle. grid = (8 r-chunks, 32 batches) = 256 blocks x 256.
// PDL: triggers its own completion immediately (so scale pre-launches), then
// waits for pool's grid before touching g_partial.
// ---------------------------------------------------------------------------
__global__ void __launch_bounds__(256) excite_kernel(
    const float* __restrict__ w1, const float* __restrict__ b1,
    const float* __restrict__ w2)
{
    cudaTriggerProgrammaticLaunchCompletion();

    const int cx = blockIdx.x;   // 0..7 (chunk of 256 r)
    const int b  = blockIdx.y;   // batch
    const int t  = threadIdx.x;  // 0..255

    __shared__ float s[CC];
    __shared__ float h[256];
    __shared__ float red[256];

    cudaGridDependencySynchronize();   // wait for pool's partials

    // stage 0: mean over spatial
    {
        const int c  = t & 127;
        const int kg = t >> 7;                 // 0 or 1 -> 28 chunks each
        float sum = 0.f;
        const float* p = g_partial + (size_t)b * CHUNKS * CC + (size_t)kg * 28 * CC + c;
        #pragma unroll 14
        for (int k = 0; k < 28; k++) sum += p[(size_t)k * CC];
        red[t] = sum;
    }
    __syncthreads();
    if (t < CC) s[t] = (red[t] + red[t + 128]) * (1.0f / (float)HW);
    __syncthreads();

    // stage 1: fc1 + gelu for r = cx*256 + t
    {
        const int r = cx * 256 + t;
        float acc = b1[r];
        #pragma unroll
        for (int c = 0; c < CC; c++)
            acc = fmaf(s[c], w1[(size_t)c * RR + r], acc);
        const float u = acc;
        const float inner = 0.7978845608028654f * (u + 0.044715f * u * u * u);
        h[t] = 0.5f * u * (1.0f + tanhf(inner));
    }
    __syncthreads();

    // stage 2: fc2 partial over this chunk's 256 r (split in two halves)
    {
        const int c    = t & 127;
        const int half = t >> 7;
        const float* hp  = h + half * 128;
        const float* w2p = w2 + ((size_t)cx * 256 + half * 128) * CC + c;
        float acc = 0.f;
        #pragma unroll 8
        for (int r = 0; r < 128; r++)
            acc = fmaf(hp[r], w2p[(size_t)r * CC], acc);
        red[t] = acc;
    }
    __syncthreads();

    if (t < CC)
        g_p2[((size_t)b * 8 + cx) * CC + t] = red[t] + red[t + 128];
}

// ---------------------------------------------------------------------------
// Kernel 3: scale. PDL: loads its x float4 BEFORE the grid-dependency sync
// (x is independent of excite), so first-wave DRAM reads overlap excite; then
// syncs, finalizes the gate (8 partials + bias -> sigmoid) and multiplies.
// ---------------------------------------------------------------------------
__global__ void __launch_bounds__(256) scale_kernel(const float* __restrict__ x,
                                                    const float* __restrict__ b2,
                                                    float* __restrict__ out) {
    const unsigned bid = blockIdx.x;
    const unsigned b   = bid / (HW * (CC / 4) / 256);   // bid / 1568
    const int t = threadIdx.x;

    const unsigned idx = bid * 256u + (unsigned)t;       // float4 index
    float4 v = ((const float4*)x)[idx];                  // pre-sync: overlaps excite

    cudaGridDependencySynchronize();                     // wait for g_p2

    __shared__ float4 sg[CC / 4];
    if (t < CC) {
        float g = b2[t];
        const float* p = g_p2 + (size_t)b * 8 * CC + t;
        #pragma unroll
        for (int j = 0; j < 8; j++) g += p[(size_t)j * CC];
        ((float*)sg)[t] = 1.0f / (1.0f + expf(-g));
    }
    __syncthreads();

    const float4 g = sg[t & 31];                         // (idx & 31) == (t & 31)
    v.x *= g.x; v.y *= g.y; v.z *= g.z; v.w *= g.w;
    ((float4*)out)[idx] = v;
}

// ---------------------------------------------------------------------------
extern "C" void kernel_launch(void* const* d_in, const int* in_sizes, int n_in,
                              void* d_out, int out_size) {
    const float* x  = (const float*)d_in[0];
    const float* w1 = (const float*)d_in[1];
    const float* b1 = (const float*)d_in[2];
    const float* w2 = (const float*)d_in[3];
    const float* b2 = (const float*)d_in[4];
    float* out = (float*)d_out;

    // Kernel 1: plain launch
    pool_kernel<<<POOL_BLOCKS + PF_BLOCKS, 256>>>(x, w1, w2);

    // Kernel 2 + 3: programmatic dependent launches (overlap ramps/tails)
    cudaLaunchAttribute attr[1];
    attr[0].id = cudaLaunchAttributeProgrammaticStreamSerialization;
    attr[0].val.programmaticStreamSerializationAllowed = 1;

    {
        cudaLaunchConfig_t cfg = {};
        cfg.gridDim  = dim3(8, BB);
        cfg.blockDim = dim3(256);
        cfg.attrs    = attr;
        cfg.numAttrs = 1;
        cudaLaunchKernelEx(&cfg, excite_kernel, w1, b1, w2);
    }
    {
        cudaLaunchConfig_t cfg = {};
        cfg.gridDim  = dim3(N4_TOTAL / 256);
        cfg.blockDim = dim3(256);
        cfg.attrs    = attr;
        cfg.numAttrs = 1;
        cudaLaunchKernelEx(&cfg, scale_kernel, x, b2, out);
    }
}